// round 7
// baseline (speedup 1.0000x reference)
#include <cuda_runtime.h>
#include <cuda_fp16.h>
#include <math.h>

// Problem constants (fixed by the dataset)
#define Bc 8
#define Nc 20000
#define Hc 15
#define Kc 25
#define Gc 64
#define Ec 640000
#define Cc 6
#define Fp 128                      // padded feature dim in GMEM planes
#define Fs 120                      // unpadded feature dim in SMEM (B*H)
#define PLANE ((size_t)Nc * Fp)     // floats per plane = 2,560,000 (10 MB)
#define EGRID 888                   // einsum grid (6 blocks/SM, 2 nodes/iter)

struct __align__(8) EdgeT { int c; float w; };

// Scratch (device globals: allocation-free rule).
// INVARIANT: g_deg and g_cursor are all-zero at kernel_launch entry.
__device__ float  g_TxAll[(size_t)Kc * PLANE];   // 256 MB: fp32 recursion planes
__device__ __half g_TxH[2][(size_t)Nc * Fp];     // fp16 gather mirrors (ping-pong)
__device__ int    g_deg[Nc];
__device__ float  g_dinv[Nc];
__device__ int    g_rowptr[Nc + 1];
__device__ int    g_cursor[Nc];
__device__ EdgeT  g_csr[Ec];
__device__ float  g_partial[EGRID * Bc * Cc];

// ---------------------------------------------------------------------------
__global__ void k_deg(const int* __restrict__ ei) {
    int e = blockIdx.x * blockDim.x + threadIdx.x;
    if (e < Ec) atomicAdd(&g_deg[ei[e]], 1);   // row = edge_index[0]
}

// dinv + single-block exclusive scan of g_deg -> g_rowptr.
// Re-zeroes g_deg and g_cursor (restores invariant; cursor consumed below).
__global__ void k_scan_dinv() {
    __shared__ int ss[1024];
    const int CH = 20;
    int tid = threadIdx.x;
    int st = tid * CH;
    int s = 0;
    #pragma unroll
    for (int i = 0; i < CH; i++) {
        int idx = st + i;
        if (idx < Nc) {
            int d = g_deg[idx];
            g_dinv[idx] = (d > 0) ? rsqrtf((float)d) : 0.0f;
            s += d;
        }
    }
    ss[tid] = s;
    __syncthreads();
    for (int off = 1; off < 1024; off <<= 1) {
        int v = (tid >= off) ? ss[tid - off] : 0;
        __syncthreads();
        ss[tid] += v;
        __syncthreads();
    }
    int run = ss[tid] - s;   // exclusive prefix of this chunk
    for (int i = 0; i < CH; i++) {
        int idx = st + i;
        if (idx < Nc) {
            int d = g_deg[idx];
            g_rowptr[idx] = run;
            run += d;
            g_deg[idx] = 0;
            g_cursor[idx] = 0;
        }
    }
    if (tid == 1023) g_rowptr[Nc] = ss[1023];
}

// Merged: CSR fill (i < Ec) + plane-0 init fp32 + fp16 mirror (buf 0).
__global__ void k_fill_init(const int* __restrict__ ei, const float* __restrict__ x) {
    int i = blockIdx.x * blockDim.x + threadIdx.x;
    if (i < Ec) {
        int r = ei[i];
        int c = ei[Ec + i];
        int pos = g_rowptr[r] + atomicAdd(&g_cursor[r], 1);
        EdgeT t;
        t.c = c;
        t.w = -(g_dinv[r] * g_dinv[c]);   // norm = -(dinv[row]*dinv[col])
        g_csr[pos] = t;
    }
    if (i < Nc * Fp) {
        int n = i >> 7, f = i & 127;
        float v = 0.0f;
        if (f < Bc * Hc) {
            int b = f / Hc, h = f - b * Hc;
            v = x[((size_t)b * Nc + n) * Hc + h];
        }
        g_TxAll[i] = v;
        g_TxH[0][i] = __float2half(v);
    }
}

// Warp-per-node CSR gather SpMM: out = (first ? L*in : 2*L*in - prev)
// fp16 mirror gather (240 B/edge); fp32 recursion state. 128-thr blocks for
// fine-grained scheduling (12 resident blocks/SM -> less tail/imbalance loss).
__global__ void __launch_bounds__(128) k_prop(int kprev, int kout, int hin, int first) {
    int warp = blockIdx.x * (blockDim.x >> 5) + (threadIdx.x >> 5);
    int lane = threadIdx.x & 31;
    if (warp >= Nc || lane >= 30) return;   // 30 lanes * 4 feat = 120 features
    const uint2* __restrict__ in2 = (const uint2*)g_TxH[hin];       // 4 halves/lane
    float4* out4 = (float4*)(g_TxAll + (size_t)kout * PLANE);
    uint2* outh = (uint2*)g_TxH[hin ^ 1];
    int s = g_rowptr[warp], e = g_rowptr[warp + 1];
    float4 acc[4];
    #pragma unroll
    for (int q = 0; q < 4; q++) acc[q] = make_float4(0.f, 0.f, 0.f, 0.f);
    int j = s;
    for (; j + 8 <= e; j += 8) {
        EdgeT E[8];
        #pragma unroll
        for (int u = 0; u < 8; u++) E[u] = g_csr[j + u];
        uint2 V[8];
        #pragma unroll
        for (int u = 0; u < 8; u++)
            V[u] = __ldg(&in2[(size_t)E[u].c * 32 + lane]);
        #pragma unroll
        for (int u = 0; u < 8; u++) {
            float w = E[u].w; int q = u & 3;
            float2 f01 = __half22float2(*(const __half2*)&V[u].x);
            float2 f23 = __half22float2(*(const __half2*)&V[u].y);
            acc[q].x = fmaf(w, f01.x, acc[q].x);
            acc[q].y = fmaf(w, f01.y, acc[q].y);
            acc[q].z = fmaf(w, f23.x, acc[q].z);
            acc[q].w = fmaf(w, f23.y, acc[q].w);
        }
    }
    for (; j + 4 <= e; j += 4) {
        EdgeT E[4];
        #pragma unroll
        for (int u = 0; u < 4; u++) E[u] = g_csr[j + u];
        uint2 V[4];
        #pragma unroll
        for (int u = 0; u < 4; u++)
            V[u] = __ldg(&in2[(size_t)E[u].c * 32 + lane]);
        #pragma unroll
        for (int u = 0; u < 4; u++) {
            float w = E[u].w;
            float2 f01 = __half22float2(*(const __half2*)&V[u].x);
            float2 f23 = __half22float2(*(const __half2*)&V[u].y);
            acc[u].x = fmaf(w, f01.x, acc[u].x);
            acc[u].y = fmaf(w, f01.y, acc[u].y);
            acc[u].z = fmaf(w, f23.x, acc[u].z);
            acc[u].w = fmaf(w, f23.y, acc[u].w);
        }
    }
    for (; j < e; j++) {
        EdgeT E0 = g_csr[j];
        uint2 V0 = __ldg(&in2[(size_t)E0.c * 32 + lane]);
        float2 f01 = __half22float2(*(const __half2*)&V0.x);
        float2 f23 = __half22float2(*(const __half2*)&V0.y);
        acc[0].x = fmaf(E0.w, f01.x, acc[0].x);
        acc[0].y = fmaf(E0.w, f01.y, acc[0].y);
        acc[0].z = fmaf(E0.w, f23.x, acc[0].z);
        acc[0].w = fmaf(E0.w, f23.y, acc[0].w);
    }
    float4 a;
    a.x = (acc[0].x + acc[1].x) + (acc[2].x + acc[3].x);
    a.y = (acc[0].y + acc[1].y) + (acc[2].y + acc[3].y);
    a.z = (acc[0].z + acc[1].z) + (acc[2].z + acc[3].z);
    a.w = (acc[0].w + acc[1].w) + (acc[2].w + acc[3].w);
    float4 r;
    if (first) {
        r = a;
    } else {
        const float4* pv = (const float4*)(g_TxAll + (size_t)kprev * PLANE);
        float4 p = pv[(size_t)warp * 32 + lane];
        r.x = fmaf(2.f, a.x, -p.x); r.y = fmaf(2.f, a.y, -p.y);
        r.z = fmaf(2.f, a.z, -p.z); r.w = fmaf(2.f, a.w, -p.w);
    }
    out4[(size_t)warp * 32 + lane] = r;
    uint2 hv;
    *(__half2*)&hv.x = __float22half2_rn(make_float2(r.x, r.y));
    *(__half2*)&hv.y = __float22half2_rn(make_float2(r.z, r.w));
    outh[(size_t)warp * 32 + lane] = hv;
}

// Fused: h[n,b,g] = relu(sum_k Tx_k[n,b,:] @ W[k] + bias); per-block logit
// partials in registers. warp = b, lane handles g = {2l, 2l+1}.
// 2-node blocking, 24 KB smem -> 6 resident blocks/SM (issue-bound kernel:
// occupancy 50% -> 75%).
__global__ void __launch_bounds__(256, 6) k_einsum(const float* __restrict__ W,
                                                  const float* __restrict__ bias,
                                                  const float* __restrict__ fc_w) {
    __shared__ float txsh[2 * Kc * Fs];   // 24.0 KB: 2 node-rows x 25 planes
    int tid = threadIdx.x;
    int b = tid >> 5, lane = tid & 31;
    float p[Cc];
    #pragma unroll
    for (int c = 0; c < Cc; c++) p[c] = 0.f;
    float bi0 = __ldg(&bias[2 * lane]);
    float bi1 = __ldg(&bias[2 * lane + 1]);
    const float4* planes = (const float4*)g_TxAll;

    for (int n0 = blockIdx.x * 2; n0 < Nc; n0 += gridDim.x * 2) {
        // Stage 25 planes x 2 nodes x 30 quads (pad quads skipped).
        float4* t4 = (float4*)txsh;
        for (int i = tid; i < Kc * 2 * 30; i += 256) {
            int k = i / 60;
            int rem = i - k * 60;
            int node = rem / 30, qq = rem - node * 30;
            t4[i] = planes[(size_t)k * (PLANE / 4) + (size_t)(n0 + node) * 32 + qq];
        }
        __syncthreads();
        float a00 = 0.f, a01 = 0.f, a10 = 0.f, a11 = 0.f;
        for (int k = 0; k < Kc; k++) {
            const float* tb0 = txsh + k * (2 * Fs) + b * Hc;   // node0
            const float* tb1 = tb0 + Fs;                        // node1
            const float2* wr = (const float2*)(W + (size_t)k * Hc * Gc);
            #pragma unroll
            for (int h = 0; h < Hc; h++) {
                float t0 = tb0[h];
                float t1 = tb1[h];
                float2 wv = __ldg(&wr[h * 32 + lane]);  // L1-resident
                a00 = fmaf(t0, wv.x, a00);
                a01 = fmaf(t0, wv.y, a01);
                a10 = fmaf(t1, wv.x, a10);
                a11 = fmaf(t1, wv.y, a11);
            }
        }
        float h00 = fmaxf(a00 + bi0, 0.f);
        float h01 = fmaxf(a01 + bi1, 0.f);
        float h10 = fmaxf(a10 + bi0, 0.f);
        float h11 = fmaxf(a11 + bi1, 0.f);
        const float* fw0 = fc_w + (size_t)n0 * Gc + 2 * lane;
        const float* fw1 = fw0 + Gc;
        #pragma unroll
        for (int c = 0; c < Cc; c++) {
            float2 w0 = __ldg((const float2*)(fw0 + (size_t)c * Nc * Gc));
            float2 w1 = __ldg((const float2*)(fw1 + (size_t)c * Nc * Gc));
            p[c] = fmaf(h00, w0.x, fmaf(h01, w0.y, p[c]));
            p[c] = fmaf(h10, w1.x, fmaf(h11, w1.y, p[c]));
        }
        __syncthreads();
    }
    #pragma unroll
    for (int c = 0; c < Cc; c++) {
        #pragma unroll
        for (int off = 16; off > 0; off >>= 1)
            p[c] += __shfl_down_sync(0xffffffffu, p[c], off);
    }
    if (lane == 0) {
        #pragma unroll
        for (int c = 0; c < Cc; c++)
            g_partial[((size_t)blockIdx.x * Bc + b) * Cc + c] = p[c];
    }
}

// Deterministic reduction of partials + fc_b + log_softmax -> d_out [8,6]
__global__ void k_final(const float* __restrict__ fc_b, float* __restrict__ out) {
    __shared__ float lg[Bc * Cc];
    int tid = threadIdx.x;
    if (tid < Bc * Cc) {
        float s = 0.f;
        for (int j = 0; j < EGRID; j++) s += g_partial[j * (Bc * Cc) + tid];
        lg[tid] = s + fc_b[tid % Cc];
    }
    __syncthreads();
    if (tid < Bc) {
        float m = -1e30f;
        #pragma unroll
        for (int c = 0; c < Cc; c++) m = fmaxf(m, lg[tid * Cc + c]);
        float se = 0.f;
        #pragma unroll
        for (int c = 0; c < Cc; c++) se += expf(lg[tid * Cc + c] - m);
        float lse = m + logf(se);
        #pragma unroll
        for (int c = 0; c < Cc; c++) out[tid * Cc + c] = lg[tid * Cc + c] - lse;
    }
}

// ---------------------------------------------------------------------------
extern "C" void kernel_launch(void* const* d_in, const int* in_sizes, int n_in,
                              void* d_out, int out_size) {
    const float* x    = (const float*)d_in[0];   // [B,N,H]
    const int*   ei   = (const int*)d_in[1];     // [2,E]
    const float* W    = (const float*)d_in[2];   // [K,H,G]
    const float* bias = (const float*)d_in[3];   // [G]
    const float* fc_w = (const float*)d_in[4];   // [C, N*G]
    const float* fc_b = (const float*)d_in[5];   // [C]
    float* out = (float*)d_out;                  // [B,C]

    k_deg<<<(Ec + 255) / 256, 256>>>(ei);                       // idx 0
    k_scan_dinv<<<1, 1024>>>();                                 // idx 1
    k_fill_init<<<(Nc * Fp + 255) / 256, 256>>>(ei, x);         // idx 2

    // Chebyshev recursion. Plane k's fp16 mirror lives in buf (k & 1).
    const int PBLK = 128;                 // 4 warps/block, warp-per-node
    const int PGRID = (Nc + 3) / 4;
    // kout=1: gather from mirror of plane0 (buf 0), write buf 1
    k_prop<<<PGRID, PBLK>>>(0, 1, 0, 1);                        // idx 3 <- ncu capture
    for (int k = 2; k < Kc; k++)
        k_prop<<<PGRID, PBLK>>>(k - 2, k, (k - 1) & 1, 0);

    k_einsum<<<EGRID, 256>>>(W, bias, fc_w);
    k_final<<<1, 64>>>(fc_b, out);
}

// round 8
// speedup vs baseline: 1.2205x; 1.2205x over previous
#include <cuda_runtime.h>
#include <cuda_fp16.h>
#include <math.h>

// Problem constants (fixed by the dataset)
#define Bc 8
#define Nc 20000
#define Hc 15
#define Kc 25
#define Gc 64
#define Ec 640000
#define Cc 6
#define Fp 128                      // padded feature dim in GMEM planes
#define Fs 120                      // unpadded feature dim in SMEM (B*H)
#define PLANE ((size_t)Nc * Fp)     // floats per plane = 2,560,000 (10 MB)
#define EGRID 592                   // einsum grid (4 nodes/iter)

struct __align__(8) EdgeT { int c; float w; };

// Scratch (device globals: allocation-free rule).
// INVARIANT: g_deg and g_cursor are all-zero at kernel_launch entry.
__device__ float  g_TxAll[(size_t)Kc * PLANE];   // 256 MB: fp32 recursion planes
__device__ __half g_TxH[2][(size_t)Nc * Fp];     // fp16 gather mirrors (ping-pong)
__device__ int    g_deg[Nc];
__device__ float  g_dinv[Nc];
__device__ int    g_rowptr[Nc + 1];
__device__ int    g_cursor[Nc];
__device__ EdgeT  g_csr[Ec];
__device__ float  g_partial[EGRID * Bc * Cc];

// ---------------------------------------------------------------------------
__global__ void k_deg(const int* __restrict__ ei) {
    int e = blockIdx.x * blockDim.x + threadIdx.x;
    if (e < Ec) atomicAdd(&g_deg[ei[e]], 1);   // row = edge_index[0]
}

// dinv + single-block exclusive scan of g_deg -> g_rowptr.
// Re-zeroes g_deg and g_cursor (restores invariant; cursor consumed below).
__global__ void k_scan_dinv() {
    __shared__ int ss[1024];
    const int CH = 20;
    int tid = threadIdx.x;
    int st = tid * CH;
    int s = 0;
    #pragma unroll
    for (int i = 0; i < CH; i++) {
        int idx = st + i;
        if (idx < Nc) {
            int d = g_deg[idx];
            g_dinv[idx] = (d > 0) ? rsqrtf((float)d) : 0.0f;
            s += d;
        }
    }
    ss[tid] = s;
    __syncthreads();
    for (int off = 1; off < 1024; off <<= 1) {
        int v = (tid >= off) ? ss[tid - off] : 0;
        __syncthreads();
        ss[tid] += v;
        __syncthreads();
    }
    int run = ss[tid] - s;   // exclusive prefix of this chunk
    for (int i = 0; i < CH; i++) {
        int idx = st + i;
        if (idx < Nc) {
            int d = g_deg[idx];
            g_rowptr[idx] = run;
            run += d;
            g_deg[idx] = 0;
            g_cursor[idx] = 0;
        }
    }
    if (tid == 1023) g_rowptr[Nc] = ss[1023];
}

// Merged: CSR fill (i < Ec) + plane-0 init fp32 + fp16 mirror (buf 0).
__global__ void k_fill_init(const int* __restrict__ ei, const float* __restrict__ x) {
    int i = blockIdx.x * blockDim.x + threadIdx.x;
    if (i < Ec) {
        int r = ei[i];
        int c = ei[Ec + i];
        int pos = g_rowptr[r] + atomicAdd(&g_cursor[r], 1);
        EdgeT t;
        t.c = c;
        t.w = -(g_dinv[r] * g_dinv[c]);   // norm = -(dinv[row]*dinv[col])
        g_csr[pos] = t;
    }
    if (i < Nc * Fp) {
        int n = i >> 7, f = i & 127;
        float v = 0.0f;
        if (f < Bc * Hc) {
            int b = f / Hc, h = f - b * Hc;
            v = x[((size_t)b * Nc + n) * Hc + h];
        }
        g_TxAll[i] = v;
        g_TxH[0][i] = __float2half(v);
    }
}

// Warp-per-node CSR gather SpMM: out = (first ? L*in : 2*L*in - prev).
// Half-warp dual-edge scheme: lanes 0-14 process even edges, lanes 15-29 odd
// edges; each lane loads uint4 (8 halves = 16 B). Per 8 edges: 4 CSR LDGs +
// 4 gather LDGs (vs 16 before) -> halved LSU issue. Cross-half shfl reduce,
// lanes 0-14 own the 120-float row for recursion update + stores.
#define PROP_MASK 0x3FFFFFFFu
__global__ void __launch_bounds__(128) k_prop(int kprev, int kout, int hin, int first) {
    int warp = blockIdx.x * (blockDim.x >> 5) + (threadIdx.x >> 5);
    int lane = threadIdx.x & 31;
    if (warp >= Nc || lane >= 30) return;
    int grp = (lane < 15) ? 0 : 1;        // which edge of the pair
    int sub = lane - grp * 15;            // feature block: halves [8*sub, 8*sub+8)
    const uint4* __restrict__ inh = (const uint4*)g_TxH[hin];   // 16 uint4/row
    int s = g_rowptr[warp], e = g_rowptr[warp + 1];
    float a0=0.f,a1=0.f,a2=0.f,a3=0.f,a4=0.f,a5=0.f,a6=0.f,a7=0.f;
    int j = s;
    for (; j + 8 <= e; j += 8) {
        EdgeT E[4];
        #pragma unroll
        for (int it = 0; it < 4; it++) E[it] = g_csr[j + 2 * it + grp];
        uint4 V[4];
        #pragma unroll
        for (int it = 0; it < 4; it++)
            V[it] = __ldg(&inh[(size_t)E[it].c * 16 + sub]);
        #pragma unroll
        for (int it = 0; it < 4; it++) {
            float w = E[it].w;
            float2 f0 = __half22float2(*(const __half2*)&V[it].x);
            float2 f1 = __half22float2(*(const __half2*)&V[it].y);
            float2 f2 = __half22float2(*(const __half2*)&V[it].z);
            float2 f3 = __half22float2(*(const __half2*)&V[it].w);
            a0 = fmaf(w, f0.x, a0); a1 = fmaf(w, f0.y, a1);
            a2 = fmaf(w, f1.x, a2); a3 = fmaf(w, f1.y, a3);
            a4 = fmaf(w, f2.x, a4); a5 = fmaf(w, f2.y, a5);
            a6 = fmaf(w, f3.x, a6); a7 = fmaf(w, f3.y, a7);
        }
    }
    for (; j + 2 <= e; j += 2) {
        EdgeT E0 = g_csr[j + grp];
        uint4 V0 = __ldg(&inh[(size_t)E0.c * 16 + sub]);
        float w = E0.w;
        float2 f0 = __half22float2(*(const __half2*)&V0.x);
        float2 f1 = __half22float2(*(const __half2*)&V0.y);
        float2 f2 = __half22float2(*(const __half2*)&V0.z);
        float2 f3 = __half22float2(*(const __half2*)&V0.w);
        a0 = fmaf(w, f0.x, a0); a1 = fmaf(w, f0.y, a1);
        a2 = fmaf(w, f1.x, a2); a3 = fmaf(w, f1.y, a3);
        a4 = fmaf(w, f2.x, a4); a5 = fmaf(w, f2.y, a5);
        a6 = fmaf(w, f3.x, a6); a7 = fmaf(w, f3.y, a7);
    }
    if (j < e && grp == 0) {               // odd trailing edge: group 0 only
        EdgeT E0 = g_csr[j];
        uint4 V0 = __ldg(&inh[(size_t)E0.c * 16 + sub]);
        float w = E0.w;
        float2 f0 = __half22float2(*(const __half2*)&V0.x);
        float2 f1 = __half22float2(*(const __half2*)&V0.y);
        float2 f2 = __half22float2(*(const __half2*)&V0.z);
        float2 f3 = __half22float2(*(const __half2*)&V0.w);
        a0 = fmaf(w, f0.x, a0); a1 = fmaf(w, f0.y, a1);
        a2 = fmaf(w, f1.x, a2); a3 = fmaf(w, f1.y, a3);
        a4 = fmaf(w, f2.x, a4); a5 = fmaf(w, f2.y, a5);
        a6 = fmaf(w, f3.x, a6); a7 = fmaf(w, f3.y, a7);
    }
    // lanes 0-14 += lanes 15-29 (same feature slice, other edge stream)
    a0 += __shfl_down_sync(PROP_MASK, a0, 15);
    a1 += __shfl_down_sync(PROP_MASK, a1, 15);
    a2 += __shfl_down_sync(PROP_MASK, a2, 15);
    a3 += __shfl_down_sync(PROP_MASK, a3, 15);
    a4 += __shfl_down_sync(PROP_MASK, a4, 15);
    a5 += __shfl_down_sync(PROP_MASK, a5, 15);
    a6 += __shfl_down_sync(PROP_MASK, a6, 15);
    a7 += __shfl_down_sync(PROP_MASK, a7, 15);
    if (grp != 0) return;
    float4* out4 = (float4*)(g_TxAll + (size_t)kout * PLANE);
    uint4* outh = (uint4*)g_TxH[hin ^ 1];
    float4 r0, r1;
    if (first) {
        r0 = make_float4(a0, a1, a2, a3);
        r1 = make_float4(a4, a5, a6, a7);
    } else {
        const float4* pv = (const float4*)(g_TxAll + (size_t)kprev * PLANE);
        float4 p0 = pv[(size_t)warp * 32 + 2 * sub];
        float4 p1 = pv[(size_t)warp * 32 + 2 * sub + 1];
        r0.x = fmaf(2.f, a0, -p0.x); r0.y = fmaf(2.f, a1, -p0.y);
        r0.z = fmaf(2.f, a2, -p0.z); r0.w = fmaf(2.f, a3, -p0.w);
        r1.x = fmaf(2.f, a4, -p1.x); r1.y = fmaf(2.f, a5, -p1.y);
        r1.z = fmaf(2.f, a6, -p1.z); r1.w = fmaf(2.f, a7, -p1.w);
    }
    out4[(size_t)warp * 32 + 2 * sub] = r0;
    out4[(size_t)warp * 32 + 2 * sub + 1] = r1;
    uint4 hv;
    *(__half2*)&hv.x = __float22half2_rn(make_float2(r0.x, r0.y));
    *(__half2*)&hv.y = __float22half2_rn(make_float2(r0.z, r0.w));
    *(__half2*)&hv.z = __float22half2_rn(make_float2(r1.x, r1.y));
    *(__half2*)&hv.w = __float22half2_rn(make_float2(r1.z, r1.w));
    outh[(size_t)warp * 16 + sub] = hv;
}

// Fused: h[n,b,g] = relu(sum_k Tx_k[n,b,:] @ W[k] + bias); per-block logit
// partials in registers. warp = b, lane handles g = {2l, 2l+1}.
// 4-node register blocking; SMEM rows unpadded (48.0 KB). NO forced
// min-blocks (R7 showed launch_bounds(256,6) causes spills: +150us).
__global__ void __launch_bounds__(256) k_einsum(const float* __restrict__ W,
                                               const float* __restrict__ bias,
                                               const float* __restrict__ fc_w) {
    __shared__ float txsh[4 * Kc * Fs];   // 48.0 KB
    int tid = threadIdx.x;
    int b = tid >> 5, lane = tid & 31;
    float p[Cc];
    #pragma unroll
    for (int c = 0; c < Cc; c++) p[c] = 0.f;
    float bi0 = __ldg(&bias[2 * lane]);
    float bi1 = __ldg(&bias[2 * lane + 1]);
    const float4* planes = (const float4*)g_TxAll;

    for (int n0 = blockIdx.x * 4; n0 < Nc; n0 += gridDim.x * 4) {
        float4* t4 = (float4*)txsh;
        for (int i = tid; i < Kc * 4 * 30; i += 256) {
            int k = i / 120;
            int rem = i - k * 120;
            int node = rem / 30, qq = rem - node * 30;
            t4[i] = planes[(size_t)k * (PLANE / 4) + (size_t)(n0 + node) * 32 + qq];
        }
        __syncthreads();
        float a[4][2];
        #pragma unroll
        for (int u = 0; u < 4; u++) { a[u][0] = 0.f; a[u][1] = 0.f; }
        for (int k = 0; k < Kc; k++) {
            const float* tb = txsh + k * (4 * Fs) + b * Hc;
            const float2* wr = (const float2*)(W + (size_t)k * Hc * Gc);
            #pragma unroll
            for (int h = 0; h < Hc; h++) {
                float t0 = tb[h];
                float t1 = tb[Fs + h];
                float t2 = tb[2 * Fs + h];
                float t3 = tb[3 * Fs + h];
                float2 wv = __ldg(&wr[h * 32 + lane]);  // L1-resident
                a[0][0] = fmaf(t0, wv.x, a[0][0]); a[0][1] = fmaf(t0, wv.y, a[0][1]);
                a[1][0] = fmaf(t1, wv.x, a[1][0]); a[1][1] = fmaf(t1, wv.y, a[1][1]);
                a[2][0] = fmaf(t2, wv.x, a[2][0]); a[2][1] = fmaf(t2, wv.y, a[2][1]);
                a[3][0] = fmaf(t3, wv.x, a[3][0]); a[3][1] = fmaf(t3, wv.y, a[3][1]);
            }
        }
        float hh[4][2];
        #pragma unroll
        for (int u = 0; u < 4; u++) {
            hh[u][0] = fmaxf(a[u][0] + bi0, 0.f);
            hh[u][1] = fmaxf(a[u][1] + bi1, 0.f);
        }
        const float* fw = fc_w + (size_t)n0 * Gc + 2 * lane;
        #pragma unroll
        for (int c = 0; c < Cc; c++) {
            const float* fwc = fw + (size_t)c * Nc * Gc;
            #pragma unroll
            for (int u = 0; u < 4; u++) {
                float2 wv = __ldg((const float2*)(fwc + u * Gc));
                p[c] = fmaf(hh[u][0], wv.x, fmaf(hh[u][1], wv.y, p[c]));
            }
        }
        __syncthreads();
    }
    #pragma unroll
    for (int c = 0; c < Cc; c++) {
        #pragma unroll
        for (int off = 16; off > 0; off >>= 1)
            p[c] += __shfl_down_sync(0xffffffffu, p[c], off);
    }
    if (lane == 0) {
        #pragma unroll
        for (int c = 0; c < Cc; c++)
            g_partial[((size_t)blockIdx.x * Bc + b) * Cc + c] = p[c];
    }
}

// Deterministic reduction of partials + fc_b + log_softmax -> d_out [8,6]
__global__ void k_final(const float* __restrict__ fc_b, float* __restrict__ out) {
    __shared__ float lg[Bc * Cc];
    int tid = threadIdx.x;
    if (tid < Bc * Cc) {
        float s = 0.f;
        for (int j = 0; j < EGRID; j++) s += g_partial[j * (Bc * Cc) + tid];
        lg[tid] = s + fc_b[tid % Cc];
    }
    __syncthreads();
    if (tid < Bc) {
        float m = -1e30f;
        #pragma unroll
        for (int c = 0; c < Cc; c++) m = fmaxf(m, lg[tid * Cc + c]);
        float se = 0.f;
        #pragma unroll
        for (int c = 0; c < Cc; c++) se += expf(lg[tid * Cc + c] - m);
        float lse = m + logf(se);
        #pragma unroll
        for (int c = 0; c < Cc; c++) out[tid * Cc + c] = lg[tid * Cc + c] - lse;
    }
}

// ---------------------------------------------------------------------------
extern "C" void kernel_launch(void* const* d_in, const int* in_sizes, int n_in,
                              void* d_out, int out_size) {
    const float* x    = (const float*)d_in[0];   // [B,N,H]
    const int*   ei   = (const int*)d_in[1];     // [2,E]
    const float* W    = (const float*)d_in[2];   // [K,H,G]
    const float* bias = (const float*)d_in[3];   // [G]
    const float* fc_w = (const float*)d_in[4];   // [C, N*G]
    const float* fc_b = (const float*)d_in[5];   // [C]
    float* out = (float*)d_out;                  // [B,C]

    k_deg<<<(Ec + 255) / 256, 256>>>(ei);                       // idx 0
    k_scan_dinv<<<1, 1024>>>();                                 // idx 1
    k_fill_init<<<(Nc * Fp + 255) / 256, 256>>>(ei, x);         // idx 2

    // Chebyshev recursion. Plane k's fp16 mirror lives in buf (k & 1).
    const int PBLK = 128;                 // 4 warps/block, warp-per-node
    const int PGRID = (Nc + 3) / 4;
    k_prop<<<PGRID, PBLK>>>(0, 1, 0, 1);                        // idx 3 <- ncu capture
    for (int k = 2; k < Kc; k++)
        k_prop<<<PGRID, PBLK>>>(k - 2, k, (k - 1) & 1, 0);

    k_einsum<<<EGRID, 256>>>(W, bias, fc_w);
    k_final<<<1, 64>>>(fc_b, out);
}

// round 11
// speedup vs baseline: 1.8460x; 1.5125x over previous
#include <cuda_runtime.h>
#include <cuda_fp16.h>
#include <stdint.h>
#include <math.h>

// Problem constants (fixed by the dataset)
#define Bc 8
#define Nc 20000
#define Hc 15
#define Kc 25
#define Gc 64
#define Ec 640000
#define Cc 6
#define Fp 128                      // feature slots per row: b*16 + h, slot h=15 == 0
#define PLANE ((size_t)Nc * Fp)     // elems per plane
#define KP 400                      // padded contraction dim: 25 planes * 16
#define EBLKS 1250                  // einsum blocks (16 nodes each)

struct __align__(8) EdgeT { int c; float w; };

// Scratch (device globals: allocation-free rule).
// INVARIANT: g_deg and g_cursor are all-zero at kernel_launch entry.
__device__ float  g_TxAll[(size_t)Kc * PLANE];            // fp32 recursion planes (256 MB)
__device__ __align__(16) __half g_TxH[Kc][PLANE];         // fp16 planes (128 MB) for gather + MMA
__device__ __align__(16) __half g_Wt[Gc * KP];            // W transposed/padded: Wt[g][pl*16+h]
__device__ int    g_deg[Nc];
__device__ float  g_dinv[Nc];
__device__ int    g_rowptr[Nc + 1];
__device__ int    g_cursor[Nc];
__device__ EdgeT  g_csr[Ec];
__device__ float  g_partial[EBLKS * Bc * Cc];

// ---------------------------------------------------------------------------
__global__ void k_deg(const int* __restrict__ ei) {
    int e = blockIdx.x * blockDim.x + threadIdx.x;
    if (e < Ec) atomicAdd(&g_deg[ei[e]], 1);   // row = edge_index[0]
}

// dinv + single-block exclusive scan of g_deg -> g_rowptr.
// Re-zeroes g_deg and g_cursor (restores invariant; cursor consumed below).
__global__ void k_scan_dinv() {
    __shared__ int ss[1024];
    const int CH = 20;
    int tid = threadIdx.x;
    int st = tid * CH;
    int s = 0;
    #pragma unroll
    for (int i = 0; i < CH; i++) {
        int idx = st + i;
        if (idx < Nc) {
            int d = g_deg[idx];
            g_dinv[idx] = (d > 0) ? rsqrtf((float)d) : 0.0f;
            s += d;
        }
    }
    ss[tid] = s;
    __syncthreads();
    for (int off = 1; off < 1024; off <<= 1) {
        int v = (tid >= off) ? ss[tid - off] : 0;
        __syncthreads();
        ss[tid] += v;
        __syncthreads();
    }
    int run = ss[tid] - s;
    for (int i = 0; i < CH; i++) {
        int idx = st + i;
        if (idx < Nc) {
            int d = g_deg[idx];
            g_rowptr[idx] = run;
            run += d;
            g_deg[idx] = 0;
            g_cursor[idx] = 0;
        }
    }
    if (tid == 1023) g_rowptr[Nc] = ss[1023];
}

// Merged: CSR fill (i < Ec) + plane-0 init (i < Nc*Fp) + Wt prep (i < Gc*KP).
// Plane layout: slot f = b*16 + h; h==15 slot is ZERO (K-pad for MMA).
__global__ void k_fill_init(const int* __restrict__ ei, const float* __restrict__ x,
                            const float* __restrict__ W) {
    int i = blockIdx.x * blockDim.x + threadIdx.x;
    if (i < Ec) {
        int r = ei[i];
        int c = ei[Ec + i];
        int pos = g_rowptr[r] + atomicAdd(&g_cursor[r], 1);
        EdgeT t;
        t.c = c;
        t.w = -(g_dinv[r] * g_dinv[c]);   // norm = -(dinv[row]*dinv[col])
        g_csr[pos] = t;
    }
    if (i < Nc * Fp) {
        int n = i >> 7, f = i & 127;
        int b = f >> 4, h = f & 15;
        float v = (h < Hc) ? x[((size_t)b * Nc + n) * Hc + h] : 0.0f;
        g_TxAll[i] = v;
        g_TxH[0][i] = __float2half(v);
    }
    if (i < Gc * KP) {   // Wt[g][pl*16 + h] = W[pl, h, g]; h==15 -> 0
        int g = i / KP, kk = i - g * KP;
        int pl = kk >> 4, h = kk & 15;
        float v = (h < Hc) ? W[((size_t)pl * Hc + h) * Gc + g] : 0.0f;
        g_Wt[i] = __float2half(v);
    }
}

// Warp-per-node CSR gather SpMM: out = (first ? L*in : 2*L*in - prev).
// Dual-edge half-warp scheme on 256 B rows: lanes 0-15 even edges, 16-31 odd;
// each lane loads uint4 (8 halves). Gather input = fp16 plane kout-1;
// prev term = fp32 plane kout-2. Writes fp32 + fp16 plane kout.
__global__ void __launch_bounds__(128) k_prop(int kout, int first) {
    int warp = blockIdx.x * (blockDim.x >> 5) + (threadIdx.x >> 5);
    int lane = threadIdx.x & 31;
    if (warp >= Nc) return;
    int grp = lane >> 4;           // which edge of the pair
    int sub = lane & 15;           // uint4 slot within the 256 B row
    const uint4* __restrict__ inh = (const uint4*)g_TxH[kout - 1];
    int s = g_rowptr[warp], e = g_rowptr[warp + 1];
    float a0=0.f,a1=0.f,a2=0.f,a3=0.f,a4=0.f,a5=0.f,a6=0.f,a7=0.f;
    int j = s;
    for (; j + 8 <= e; j += 8) {
        EdgeT E[4];
        #pragma unroll
        for (int it = 0; it < 4; it++) E[it] = g_csr[j + 2 * it + grp];
        uint4 V[4];
        #pragma unroll
        for (int it = 0; it < 4; it++)
            V[it] = __ldg(&inh[(size_t)E[it].c * 16 + sub]);
        #pragma unroll
        for (int it = 0; it < 4; it++) {
            float w = E[it].w;
            float2 f0 = __half22float2(*(const __half2*)&V[it].x);
            float2 f1 = __half22float2(*(const __half2*)&V[it].y);
            float2 f2 = __half22float2(*(const __half2*)&V[it].z);
            float2 f3 = __half22float2(*(const __half2*)&V[it].w);
            a0 = fmaf(w, f0.x, a0); a1 = fmaf(w, f0.y, a1);
            a2 = fmaf(w, f1.x, a2); a3 = fmaf(w, f1.y, a3);
            a4 = fmaf(w, f2.x, a4); a5 = fmaf(w, f2.y, a5);
            a6 = fmaf(w, f3.x, a6); a7 = fmaf(w, f3.y, a7);
        }
    }
    for (; j + 2 <= e; j += 2) {
        EdgeT E0 = g_csr[j + grp];
        uint4 V0 = __ldg(&inh[(size_t)E0.c * 16 + sub]);
        float w = E0.w;
        float2 f0 = __half22float2(*(const __half2*)&V0.x);
        float2 f1 = __half22float2(*(const __half2*)&V0.y);
        float2 f2 = __half22float2(*(const __half2*)&V0.z);
        float2 f3 = __half22float2(*(const __half2*)&V0.w);
        a0 = fmaf(w, f0.x, a0); a1 = fmaf(w, f0.y, a1);
        a2 = fmaf(w, f1.x, a2); a3 = fmaf(w, f1.y, a3);
        a4 = fmaf(w, f2.x, a4); a5 = fmaf(w, f2.y, a5);
        a6 = fmaf(w, f3.x, a6); a7 = fmaf(w, f3.y, a7);
    }
    if (j < e && grp == 0) {               // odd trailing edge
        EdgeT E0 = g_csr[j];
        uint4 V0 = __ldg(&inh[(size_t)E0.c * 16 + sub]);
        float w = E0.w;
        float2 f0 = __half22float2(*(const __half2*)&V0.x);
        float2 f1 = __half22float2(*(const __half2*)&V0.y);
        float2 f2 = __half22float2(*(const __half2*)&V0.z);
        float2 f3 = __half22float2(*(const __half2*)&V0.w);
        a0 = fmaf(w, f0.x, a0); a1 = fmaf(w, f0.y, a1);
        a2 = fmaf(w, f1.x, a2); a3 = fmaf(w, f1.y, a3);
        a4 = fmaf(w, f2.x, a4); a5 = fmaf(w, f2.y, a5);
        a6 = fmaf(w, f3.x, a6); a7 = fmaf(w, f3.y, a7);
    }
    a0 += __shfl_down_sync(0xffffffffu, a0, 16);
    a1 += __shfl_down_sync(0xffffffffu, a1, 16);
    a2 += __shfl_down_sync(0xffffffffu, a2, 16);
    a3 += __shfl_down_sync(0xffffffffu, a3, 16);
    a4 += __shfl_down_sync(0xffffffffu, a4, 16);
    a5 += __shfl_down_sync(0xffffffffu, a5, 16);
    a6 += __shfl_down_sync(0xffffffffu, a6, 16);
    a7 += __shfl_down_sync(0xffffffffu, a7, 16);
    if (grp != 0) return;
    float4* out4 = (float4*)(g_TxAll + (size_t)kout * PLANE);
    uint4* outh = (uint4*)g_TxH[kout];
    float4 r0, r1;
    if (first) {
        r0 = make_float4(a0, a1, a2, a3);
        r1 = make_float4(a4, a5, a6, a7);
    } else {
        const float4* pv = (const float4*)(g_TxAll + (size_t)(kout - 2) * PLANE);
        float4 p0 = pv[(size_t)warp * 32 + 2 * sub];
        float4 p1 = pv[(size_t)warp * 32 + 2 * sub + 1];
        r0.x = fmaf(2.f, a0, -p0.x); r0.y = fmaf(2.f, a1, -p0.y);
        r0.z = fmaf(2.f, a2, -p0.z); r0.w = fmaf(2.f, a3, -p0.w);
        r1.x = fmaf(2.f, a4, -p1.x); r1.y = fmaf(2.f, a5, -p1.y);
        r1.z = fmaf(2.f, a6, -p1.z); r1.w = fmaf(2.f, a7, -p1.w);
    }
    out4[(size_t)warp * 32 + 2 * sub] = r0;
    out4[(size_t)warp * 32 + 2 * sub + 1] = r1;
    uint4 hv;
    *(__half2*)&hv.x = __float22half2_rn(make_float2(r0.x, r0.y));
    *(__half2*)&hv.y = __float22half2_rn(make_float2(r0.z, r0.w));
    *(__half2*)&hv.z = __float22half2_rn(make_float2(r1.x, r1.y));
    *(__half2*)&hv.w = __float22half2_rn(make_float2(r1.z, r1.w));
    outh[(size_t)warp * 16 + sub] = hv;
}

// Tensor-core einsum + relu + FC partial logits.
// GEMM: h[(n,b), g] = sum over 25 k-tiles of A(16x16 fp16) x Wt(16x8 fp16),
// mma.m16n8k16, fp32 accum. Warp tile = 2 nodes (16 rows) x 64 g.
// M-rows: m = b (node n0) and m+8 = b (node n0+1). C cols g = s*8 + lq*2.
// Epilogue: bias+relu, dot with fc_w, quad-reduce, block-reduce to partials.
__global__ void __launch_bounds__(256) k_einsum(const float* __restrict__ bias,
                                               const float* __restrict__ fc_w) {
    __shared__ float ps[8][Bc * Cc];
    int tid = threadIdx.x, wid = tid >> 5, lane = tid & 31;
    int lq = lane & 3, lg = lane >> 2;            // quad idx / group id
    int wg = blockIdx.x * 8 + wid;                // global warp id, 0..9999
    int n0 = wg * 2;
    float acc[8][4];
    #pragma unroll
    for (int s = 0; s < 8; s++)
        #pragma unroll
        for (int q = 0; q < 4; q++) acc[s][q] = 0.f;
    size_t rowlo = (size_t)n0 * Fp + lg * 16;     // A row (n0, b=lg)
    int h0 = lq * 2;
    for (int pl = 0; pl < Kc; pl++) {
        const __half* P = g_TxH[pl];
        uint32_t a0 = *(const uint32_t*)(P + rowlo + h0);
        uint32_t a1 = *(const uint32_t*)(P + rowlo + Fp + h0);
        uint32_t a2 = *(const uint32_t*)(P + rowlo + h0 + 8);
        uint32_t a3 = *(const uint32_t*)(P + rowlo + Fp + h0 + 8);
        #pragma unroll
        for (int s = 0; s < 8; s++) {
            const __half* wb = g_Wt + (size_t)(s * 8 + lg) * KP + pl * 16 + h0;
            uint32_t b0 = *(const uint32_t*)(wb);
            uint32_t b1 = *(const uint32_t*)(wb + 8);
            asm volatile(
                "mma.sync.aligned.m16n8k16.row.col.f32.f16.f16.f32 "
                "{%0,%1,%2,%3}, {%4,%5,%6,%7}, {%8,%9}, {%0,%1,%2,%3};"
                : "+f"(acc[s][0]), "+f"(acc[s][1]), "+f"(acc[s][2]), "+f"(acc[s][3])
                : "r"(a0), "r"(a1), "r"(a2), "r"(a3), "r"(b0), "r"(b1));
        }
    }
    float p[Cc];
    #pragma unroll
    for (int c = 0; c < Cc; c++) p[c] = 0.f;
    #pragma unroll
    for (int s = 0; s < 8; s++) {
        int g0 = s * 8 + lq * 2;
        float2 bi = __ldg((const float2*)(bias + g0));
        float hl0 = fmaxf(acc[s][0] + bi.x, 0.f);
        float hl1 = fmaxf(acc[s][1] + bi.y, 0.f);
        float hh0 = fmaxf(acc[s][2] + bi.x, 0.f);
        float hh1 = fmaxf(acc[s][3] + bi.y, 0.f);
        #pragma unroll
        for (int c = 0; c < Cc; c++) {
            const float* fwc = fc_w + (size_t)c * Nc * Gc + (size_t)n0 * Gc + g0;
            float2 wlo = __ldg((const float2*)(fwc));
            float2 whi = __ldg((const float2*)(fwc + Gc));
            p[c] = fmaf(hl0, wlo.x, fmaf(hl1, wlo.y, p[c]));
            p[c] = fmaf(hh0, whi.x, fmaf(hh1, whi.y, p[c]));
        }
    }
    #pragma unroll
    for (int c = 0; c < Cc; c++) {
        p[c] += __shfl_xor_sync(0xffffffffu, p[c], 1);
        p[c] += __shfl_xor_sync(0xffffffffu, p[c], 2);
    }
    if (lq == 0) {
        #pragma unroll
        for (int c = 0; c < Cc; c++) ps[wid][lg * Cc + c] = p[c];
    }
    __syncthreads();
    if (tid < Bc * Cc) {
        float s = 0.f;
        #pragma unroll
        for (int w = 0; w < 8; w++) s += ps[w][tid];
        g_partial[(size_t)blockIdx.x * (Bc * Cc) + tid] = s;
    }
}

// Deterministic reduction of 1250x48 partials + fc_b + log_softmax -> [8,6]
__global__ void k_final(const float* __restrict__ fc_b, float* __restrict__ out) {
    __shared__ float red[480];
    __shared__ float lg[Bc * Cc];
    int t = threadIdx.x;   // 512
    if (t < 480) {
        int col = t % 48, grp = t / 48;   // 10 groups
        float s = 0.f;
        for (int r = grp; r < EBLKS; r += 10)
            s += g_partial[(size_t)r * 48 + col];
        red[t] = s;
    }
    __syncthreads();
    if (t < 48) {
        float s = 0.f;
        #pragma unroll
        for (int g = 0; g < 10; g++) s += red[g * 48 + t];
        lg[t] = s + fc_b[t % Cc];
    }
    __syncthreads();
    if (t < Bc) {
        float m = -1e30f;
        #pragma unroll
        for (int c = 0; c < Cc; c++) m = fmaxf(m, lg[t * Cc + c]);
        float se = 0.f;
        #pragma unroll
        for (int c = 0; c < Cc; c++) se += expf(lg[t * Cc + c] - m);
        float lse = m + logf(se);
        #pragma unroll
        for (int c = 0; c < Cc; c++) out[t * Cc + c] = lg[t * Cc + c] - lse;
    }
}

// ---------------------------------------------------------------------------
extern "C" void kernel_launch(void* const* d_in, const int* in_sizes, int n_in,
                              void* d_out, int out_size) {
    const float* x    = (const float*)d_in[0];   // [B,N,H]
    const int*   ei   = (const int*)d_in[1];     // [2,E]
    const float* W    = (const float*)d_in[2];   // [K,H,G]
    const float* bias = (const float*)d_in[3];   // [G]
    const float* fc_w = (const float*)d_in[4];   // [C, N*G]
    const float* fc_b = (const float*)d_in[5];   // [C]
    float* out = (float*)d_out;                  // [B,C]

    k_deg<<<(Ec + 255) / 256, 256>>>(ei);                        // idx 0
    k_scan_dinv<<<1, 1024>>>();                                  // idx 1
    k_fill_init<<<(Nc * Fp + 255) / 256, 256>>>(ei, x, W);       // idx 2

    // Chebyshev recursion: plane k from fp16 plane k-1 (+ fp32 plane k-2)
    const int PBLK = 128;
    const int PGRID = (Nc + 3) / 4;
    k_prop<<<PGRID, PBLK>>>(1, 1);                               // idx 3 <- ncu capture
    for (int k = 2; k < Kc; k++)
        k_prop<<<PGRID, PBLK>>>(k, 0);

    k_einsum<<<EBLKS, 256>>>(bias, fc_w);
    k_final<<<1, 512>>>(fc_b, out);
}

// round 12
// speedup vs baseline: 1.8522x; 1.0033x over previous
#include <cuda_runtime.h>
#include <cuda_fp16.h>
#include <stdint.h>
#include <math.h>

// Problem constants (fixed by the dataset)
#define Bc 8
#define Nc 20000
#define Hc 15
#define Kc 25
#define Gc 64
#define Ec 640000
#define Cc 6
#define Fp 128                      // feature slots per row: b*16 + h, slot h=15 == 0
#define PLANE ((size_t)Nc * Fp)     // elems per plane
#define KP 400                      // padded contraction dim: 25 planes * 16
#define EBLKS 1250                  // einsum blocks (16 nodes each)

struct __align__(8) EdgeT { int c; float w; };

// Scratch (device globals: allocation-free rule).
// INVARIANT: g_deg and g_cursor are all-zero at kernel_launch entry.
// fp32 recursion state: TWO parity ping-pong buffers updated IN PLACE
// (T_k overwrites T_{k-2}, same parity; each warp touches only its own row).
// 20 MB total -> permanently L2-resident, no DRAM streaming.
__device__ float  g_TxF[2][PLANE];                        // fp32 parity buffers
__device__ __align__(16) __half g_TxH[Kc][PLANE];         // fp16 planes (128 MB): gather + MMA
__device__ __align__(16) __half g_Wt[Gc * KP];            // W transposed/padded: Wt[g][pl*16+h]
__device__ int    g_deg[Nc];
__device__ float  g_dinv[Nc];
__device__ int    g_rowptr[Nc + 1];
__device__ int    g_cursor[Nc];
__device__ EdgeT  g_csr[Ec];
__device__ float  g_partial[EBLKS * Bc * Cc];

// ---------------------------------------------------------------------------
__global__ void k_deg(const int* __restrict__ ei) {
    int e = blockIdx.x * blockDim.x + threadIdx.x;
    if (e < Ec) atomicAdd(&g_deg[ei[e]], 1);   // row = edge_index[0]
}

// dinv + single-block exclusive scan of g_deg -> g_rowptr.
// Re-zeroes g_deg and g_cursor (restores invariant; cursor consumed below).
__global__ void k_scan_dinv() {
    __shared__ int ss[1024];
    const int CH = 20;
    int tid = threadIdx.x;
    int st = tid * CH;
    int s = 0;
    #pragma unroll
    for (int i = 0; i < CH; i++) {
        int idx = st + i;
        if (idx < Nc) {
            int d = g_deg[idx];
            g_dinv[idx] = (d > 0) ? rsqrtf((float)d) : 0.0f;
            s += d;
        }
    }
    ss[tid] = s;
    __syncthreads();
    for (int off = 1; off < 1024; off <<= 1) {
        int v = (tid >= off) ? ss[tid - off] : 0;
        __syncthreads();
        ss[tid] += v;
        __syncthreads();
    }
    int run = ss[tid] - s;
    for (int i = 0; i < CH; i++) {
        int idx = st + i;
        if (idx < Nc) {
            int d = g_deg[idx];
            g_rowptr[idx] = run;
            run += d;
            g_deg[idx] = 0;
            g_cursor[idx] = 0;
        }
    }
    if (tid == 1023) g_rowptr[Nc] = ss[1023];
}

// Merged: CSR fill (i < Ec) + plane-0 init (i < Nc*Fp) + Wt prep (i < Gc*KP).
// Plane layout: slot f = b*16 + h; h==15 slot is ZERO (K-pad for MMA).
__global__ void k_fill_init(const int* __restrict__ ei, const float* __restrict__ x,
                            const float* __restrict__ W) {
    int i = blockIdx.x * blockDim.x + threadIdx.x;
    if (i < Ec) {
        int r = ei[i];
        int c = ei[Ec + i];
        int pos = g_rowptr[r] + atomicAdd(&g_cursor[r], 1);
        EdgeT t;
        t.c = c;
        t.w = -(g_dinv[r] * g_dinv[c]);   // norm = -(dinv[row]*dinv[col])
        g_csr[pos] = t;
    }
    if (i < Nc * Fp) {
        int n = i >> 7, f = i & 127;
        int b = f >> 4, h = f & 15;
        float v = (h < Hc) ? x[((size_t)b * Nc + n) * Hc + h] : 0.0f;
        g_TxF[0][i] = v;                  // T_0 -> parity-0 buffer
        g_TxH[0][i] = __float2half(v);
    }
    if (i < Gc * KP) {   // Wt[g][pl*16 + h] = W[pl, h, g]; h==15 -> 0
        int g = i / KP, kk = i - g * KP;
        int pl = kk >> 4, h = kk & 15;
        float v = (h < Hc) ? W[((size_t)pl * Hc + h) * Gc + g] : 0.0f;
        g_Wt[i] = __float2half(v);
    }
}

// Warp-per-node CSR gather SpMM: out = (first ? L*in : 2*L*in - prev).
// Dual-edge half-warp scheme on 256 B rows: lanes 0-15 even edges, 16-31 odd;
// each lane loads uint4 (8 halves). Gather input = fp16 plane kout-1.
// prev = fp32 parity buffer [kout&1] (holds T_{kout-2}); result overwrites it
// IN PLACE (same row, same warp -> race-free) + writes fp16 plane kout.
__global__ void __launch_bounds__(128) k_prop(int kout, int first) {
    int warp = blockIdx.x * (blockDim.x >> 5) + (threadIdx.x >> 5);
    int lane = threadIdx.x & 31;
    if (warp >= Nc) return;
    int grp = lane >> 4;           // which edge of the pair
    int sub = lane & 15;           // uint4 slot within the 256 B row
    const uint4* __restrict__ inh = (const uint4*)g_TxH[kout - 1];
    int s = g_rowptr[warp], e = g_rowptr[warp + 1];
    float a0=0.f,a1=0.f,a2=0.f,a3=0.f,a4=0.f,a5=0.f,a6=0.f,a7=0.f;
    int j = s;
    for (; j + 8 <= e; j += 8) {
        EdgeT E[4];
        #pragma unroll
        for (int it = 0; it < 4; it++) E[it] = g_csr[j + 2 * it + grp];
        uint4 V[4];
        #pragma unroll
        for (int it = 0; it < 4; it++)
            V[it] = __ldg(&inh[(size_t)E[it].c * 16 + sub]);
        #pragma unroll
        for (int it = 0; it < 4; it++) {
            float w = E[it].w;
            float2 f0 = __half22float2(*(const __half2*)&V[it].x);
            float2 f1 = __half22float2(*(const __half2*)&V[it].y);
            float2 f2 = __half22float2(*(const __half2*)&V[it].z);
            float2 f3 = __half22float2(*(const __half2*)&V[it].w);
            a0 = fmaf(w, f0.x, a0); a1 = fmaf(w, f0.y, a1);
            a2 = fmaf(w, f1.x, a2); a3 = fmaf(w, f1.y, a3);
            a4 = fmaf(w, f2.x, a4); a5 = fmaf(w, f2.y, a5);
            a6 = fmaf(w, f3.x, a6); a7 = fmaf(w, f3.y, a7);
        }
    }
    for (; j + 2 <= e; j += 2) {
        EdgeT E0 = g_csr[j + grp];
        uint4 V0 = __ldg(&inh[(size_t)E0.c * 16 + sub]);
        float w = E0.w;
        float2 f0 = __half22float2(*(const __half2*)&V0.x);
        float2 f1 = __half22float2(*(const __half2*)&V0.y);
        float2 f2 = __half22float2(*(const __half2*)&V0.z);
        float2 f3 = __half22float2(*(const __half2*)&V0.w);
        a0 = fmaf(w, f0.x, a0); a1 = fmaf(w, f0.y, a1);
        a2 = fmaf(w, f1.x, a2); a3 = fmaf(w, f1.y, a3);
        a4 = fmaf(w, f2.x, a4); a5 = fmaf(w, f2.y, a5);
        a6 = fmaf(w, f3.x, a6); a7 = fmaf(w, f3.y, a7);
    }
    if (j < e && grp == 0) {               // odd trailing edge
        EdgeT E0 = g_csr[j];
        uint4 V0 = __ldg(&inh[(size_t)E0.c * 16 + sub]);
        float w = E0.w;
        float2 f0 = __half22float2(*(const __half2*)&V0.x);
        float2 f1 = __half22float2(*(const __half2*)&V0.y);
        float2 f2 = __half22float2(*(const __half2*)&V0.z);
        float2 f3 = __half22float2(*(const __half2*)&V0.w);
        a0 = fmaf(w, f0.x, a0); a1 = fmaf(w, f0.y, a1);
        a2 = fmaf(w, f1.x, a2); a3 = fmaf(w, f1.y, a3);
        a4 = fmaf(w, f2.x, a4); a5 = fmaf(w, f2.y, a5);
        a6 = fmaf(w, f3.x, a6); a7 = fmaf(w, f3.y, a7);
    }
    a0 += __shfl_down_sync(0xffffffffu, a0, 16);
    a1 += __shfl_down_sync(0xffffffffu, a1, 16);
    a2 += __shfl_down_sync(0xffffffffu, a2, 16);
    a3 += __shfl_down_sync(0xffffffffu, a3, 16);
    a4 += __shfl_down_sync(0xffffffffu, a4, 16);
    a5 += __shfl_down_sync(0xffffffffu, a5, 16);
    a6 += __shfl_down_sync(0xffffffffu, a6, 16);
    a7 += __shfl_down_sync(0xffffffffu, a7, 16);
    if (grp != 0) return;
    float4* buf = (float4*)g_TxF[kout & 1];      // prev in, result out (in place)
    uint4* outh = (uint4*)g_TxH[kout];
    float4 r0, r1;
    if (first) {
        r0 = make_float4(a0, a1, a2, a3);
        r1 = make_float4(a4, a5, a6, a7);
    } else {
        float4 p0 = buf[(size_t)warp * 32 + 2 * sub];
        float4 p1 = buf[(size_t)warp * 32 + 2 * sub + 1];
        r0.x = fmaf(2.f, a0, -p0.x); r0.y = fmaf(2.f, a1, -p0.y);
        r0.z = fmaf(2.f, a2, -p0.z); r0.w = fmaf(2.f, a3, -p0.w);
        r1.x = fmaf(2.f, a4, -p1.x); r1.y = fmaf(2.f, a5, -p1.y);
        r1.z = fmaf(2.f, a6, -p1.z); r1.w = fmaf(2.f, a7, -p1.w);
    }
    buf[(size_t)warp * 32 + 2 * sub] = r0;
    buf[(size_t)warp * 32 + 2 * sub + 1] = r1;
    uint4 hv;
    *(__half2*)&hv.x = __float22half2_rn(make_float2(r0.x, r0.y));
    *(__half2*)&hv.y = __float22half2_rn(make_float2(r0.z, r0.w));
    *(__half2*)&hv.z = __float22half2_rn(make_float2(r1.x, r1.y));
    *(__half2*)&hv.w = __float22half2_rn(make_float2(r1.z, r1.w));
    outh[(size_t)warp * 16 + sub] = hv;
}

// Tensor-core einsum + relu + FC partial logits.
// GEMM: h[(n,b), g] = sum over 25 k-tiles of A(16x16 fp16) x Wt(16x8 fp16),
// mma.m16n8k16, fp32 accum. Warp tile = 2 nodes (16 rows) x 64 g.
// M-rows: m = b (node n0) and m+8 = b (node n0+1). C cols g = s*8 + lq*2.
// Epilogue: bias+relu, dot with fc_w, quad-reduce, block-reduce to partials.
__global__ void __launch_bounds__(256) k_einsum(const float* __restrict__ bias,
                                               const float* __restrict__ fc_w) {
    __shared__ float ps[8][Bc * Cc];
    int tid = threadIdx.x, wid = tid >> 5, lane = tid & 31;
    int lq = lane & 3, lg = lane >> 2;            // quad idx / group id
    int wg = blockIdx.x * 8 + wid;                // global warp id, 0..9999
    int n0 = wg * 2;
    float acc[8][4];
    #pragma unroll
    for (int s = 0; s < 8; s++)
        #pragma unroll
        for (int q = 0; q < 4; q++) acc[s][q] = 0.f;
    size_t rowlo = (size_t)n0 * Fp + lg * 16;     // A row (n0, b=lg)
    int h0 = lq * 2;
    for (int pl = 0; pl < Kc; pl++) {
        const __half* P = g_TxH[pl];
        uint32_t a0 = *(const uint32_t*)(P + rowlo + h0);
        uint32_t a1 = *(const uint32_t*)(P + rowlo + Fp + h0);
        uint32_t a2 = *(const uint32_t*)(P + rowlo + h0 + 8);
        uint32_t a3 = *(const uint32_t*)(P + rowlo + Fp + h0 + 8);
        #pragma unroll
        for (int s = 0; s < 8; s++) {
            const __half* wb = g_Wt + (size_t)(s * 8 + lg) * KP + pl * 16 + h0;
            uint32_t b0 = *(const uint32_t*)(wb);
            uint32_t b1 = *(const uint32_t*)(wb + 8);
            asm volatile(
                "mma.sync.aligned.m16n8k16.row.col.f32.f16.f16.f32 "
                "{%0,%1,%2,%3}, {%4,%5,%6,%7}, {%8,%9}, {%0,%1,%2,%3};"
                : "+f"(acc[s][0]), "+f"(acc[s][1]), "+f"(acc[s][2]), "+f"(acc[s][3])
                : "r"(a0), "r"(a1), "r"(a2), "r"(a3), "r"(b0), "r"(b1));
        }
    }
    float p[Cc];
    #pragma unroll
    for (int c = 0; c < Cc; c++) p[c] = 0.f;
    #pragma unroll
    for (int s = 0; s < 8; s++) {
        int g0 = s * 8 + lq * 2;
        float2 bi = __ldg((const float2*)(bias + g0));
        float hl0 = fmaxf(acc[s][0] + bi.x, 0.f);
        float hl1 = fmaxf(acc[s][1] + bi.y, 0.f);
        float hh0 = fmaxf(acc[s][2] + bi.x, 0.f);
        float hh1 = fmaxf(acc[s][3] + bi.y, 0.f);
        #pragma unroll
        for (int c = 0; c < Cc; c++) {
            const float* fwc = fc_w + (size_t)c * Nc * Gc + (size_t)n0 * Gc + g0;
            float2 wlo = __ldg((const float2*)(fwc));
            float2 whi = __ldg((const float2*)(fwc + Gc));
            p[c] = fmaf(hl0, wlo.x, fmaf(hl1, wlo.y, p[c]));
            p[c] = fmaf(hh0, whi.x, fmaf(hh1, whi.y, p[c]));
        }
    }
    #pragma unroll
    for (int c = 0; c < Cc; c++) {
        p[c] += __shfl_xor_sync(0xffffffffu, p[c], 1);
        p[c] += __shfl_xor_sync(0xffffffffu, p[c], 2);
    }
    if (lq == 0) {
        #pragma unroll
        for (int c = 0; c < Cc; c++) ps[wid][lg * Cc + c] = p[c];
    }
    __syncthreads();
    if (tid < Bc * Cc) {
        float s = 0.f;
        #pragma unroll
        for (int w = 0; w < 8; w++) s += ps[w][tid];
        g_partial[(size_t)blockIdx.x * (Bc * Cc) + tid] = s;
    }
}

// Deterministic reduction of 1250x48 partials + fc_b + log_softmax -> [8,6]
__global__ void k_final(const float* __restrict__ fc_b, float* __restrict__ out) {
    __shared__ float red[480];
    __shared__ float lg[Bc * Cc];
    int t = threadIdx.x;   // 512
    if (t < 480) {
        int col = t % 48, grp = t / 48;   // 10 groups
        float s = 0.f;
        for (int r = grp; r < EBLKS; r += 10)
            s += g_partial[(size_t)r * 48 + col];
        red[t] = s;
    }
    __syncthreads();
    if (t < 48) {
        float s = 0.f;
        #pragma unroll
        for (int g = 0; g < 10; g++) s += red[g * 48 + t];
        lg[t] = s + fc_b[t % Cc];
    }
    __syncthreads();
    if (t < Bc) {
        float m = -1e30f;
        #pragma unroll
        for (int c = 0; c < Cc; c++) m = fmaxf(m, lg[t * Cc + c]);
        float se = 0.f;
        #pragma unroll
        for (int c = 0; c < Cc; c++) se += expf(lg[t * Cc + c] - m);
        float lse = m + logf(se);
        #pragma unroll
        for (int c = 0; c < Cc; c++) out[t * Cc + c] = lg[t * Cc + c] - lse;
    }
}

// ---------------------------------------------------------------------------
extern "C" void kernel_launch(void* const* d_in, const int* in_sizes, int n_in,
                              void* d_out, int out_size) {
    const float* x    = (const float*)d_in[0];   // [B,N,H]
    const int*   ei   = (const int*)d_in[1];     // [2,E]
    const float* W    = (const float*)d_in[2];   // [K,H,G]
    const float* bias = (const float*)d_in[3];   // [G]
    const float* fc_w = (const float*)d_in[4];   // [C, N*G]
    const float* fc_b = (const float*)d_in[5];   // [C]
    float* out = (float*)d_out;                  // [B,C]

    k_deg<<<(Ec + 255) / 256, 256>>>(ei);                        // idx 0
    k_scan_dinv<<<1, 1024>>>();                                  // idx 1
    k_fill_init<<<(Nc * Fp + 255) / 256, 256>>>(ei, x, W);       // idx 2

    // Chebyshev recursion: plane k from fp16 plane k-1; fp32 parity buffers
    const int PBLK = 128;
    const int PGRID = (Nc + 3) / 4;
    k_prop<<<PGRID, PBLK>>>(1, 1);                               // idx 3 <- ncu capture
    for (int k = 2; k < Kc; k++)
        k_prop<<<PGRID, PBLK>>>(k, 0);

    k_einsum<<<EBLKS, 256>>>(bias, fc_w);
    k_final<<<1, 512>>>(fc_b, out);
}